// round 3
// baseline (speedup 1.0000x reference)
#include <cuda_runtime.h>

#define B_ 128
#define T_ 4096
#define I_ 64
#define H_ 128
#define G_ 384   /* 3*H */
#define C_ 2
#define ALPHA_ 0.3f
#define BETA_  0.5f

#define CH_   256   /* EMA chunk length  */
#define HALO_ 64    /* EMA warm-up halo: trunc err ~0.5^64 */

// Scratch (device globals: allocation-free per harness rules)
__device__ float g_x2[(long)B_ * T_ * I_];            // 134 MB
__device__ float g_xp[(long)B_ * T_ * G_ + 2 * G_];   // 805 MB (+2-row pad for prefetch)
__device__ float g_st11[B_ * C_];
__device__ float g_st12[B_ * C_];

// ---------------- packed f32x2 helpers (sm_100+) ----------------
__device__ __forceinline__ unsigned long long pack2_(float lo, float hi) {
    unsigned long long r;
    asm("mov.b64 %0, {%1, %2};" : "=l"(r) : "f"(lo), "f"(hi));
    return r;
}
__device__ __forceinline__ float2 unpack2_(unsigned long long v) {
    float2 r;
    asm("mov.b64 {%0, %1}, %2;" : "=f"(r.x), "=f"(r.y) : "l"(v));
    return r;
}
__device__ __forceinline__ void fma2_(unsigned long long& d,
                                      unsigned long long a,
                                      unsigned long long b) {
    asm("fma.rn.f32x2 %0, %1, %2, %0;" : "+l"(d) : "l"(a), "l"(b));
}

__device__ __forceinline__ float sigm_(float x) {
    x = fminf(fmaxf(x, -30.f), 30.f);
    float e = __expf(-x);
    return __fdividef(1.f, 1.f + e);
}
__device__ __forceinline__ float tanh_(float x) {
    x = fminf(fmaxf(x, -15.f), 15.f);
    float e = __expf(-2.f * x);
    return __fdividef(1.f - e, 1.f + e);
}

// ---------------------------------------------------------------------------
// Kernel 1: chained EMAs, chunked-parallel with decay halo.
// ---------------------------------------------------------------------------
__global__ __launch_bounds__(64) void ema_kernel(const float* __restrict__ x) {
    int nchunk = T_ / CH_;
    int c = blockIdx.x % nchunk;
    int b = blockIdx.x / nchunk;
    int i = threadIdx.x;

    const float* xin = x + (long)b * T_ * I_ + i;
    float* o = g_x2 + (long)b * T_ * I_ + i;

    int t0 = c * CH_;
    int ts = (c == 0) ? 0 : (t0 - HALO_);

    float x1 = xin[(long)ts * I_];
    float x2 = x1;

#pragma unroll 4
    for (int t = ts + 1; t < t0; ++t) {
        float xt = xin[(long)t * I_];
        x1 = fmaf(ALPHA_, x1, (1.f - ALPHA_) * xt);
        x2 = fmaf(BETA_, x2, (1.f - BETA_) * x1);
    }

    if (c == 0) o[0] = x2;
    int tb = (c == 0) ? 1 : t0;
#pragma unroll 4
    for (int t = tb; t < t0 + CH_; ++t) {
        float xt = xin[(long)t * I_];
        x1 = fmaf(ALPHA_, x1, (1.f - ALPHA_) * xt);
        x2 = fmaf(BETA_, x2, (1.f - BETA_) * x1);
        o[(long)t * I_] = x2;
    }

    if (c == nchunk - 1 && (i == 1 || i == 2)) {
        g_st11[b * C_ + (i - 1)] = x1;
        g_st12[b * C_ + (i - 1)] = x2;
    }
}

// ---------------------------------------------------------------------------
// Kernel 2: xp[m, g] = b_ih[g] + sum_k x2[m, k] * W_ih[g, k]   (f32x2 packed)
// ---------------------------------------------------------------------------
__global__ __launch_bounds__(384) void xp_gemm_kernel(
    const float* __restrict__ W_ih, const float* __restrict__ b_ih) {
    __shared__ __align__(16) float xs[64 * I_];  // 16 KB
    int m0 = blockIdx.x * 64;
    int g = threadIdx.x;

    {
        const float4* src = (const float4*)(g_x2 + (long)m0 * I_);
        float4* dst = (float4*)xs;
        for (int idx = g; idx < (64 * I_) / 4; idx += 384) dst[idx] = src[idx];
    }

    unsigned long long w2[I_ / 2];
    {
        const unsigned long long* wrow =
            (const unsigned long long*)(W_ih + g * I_);
#pragma unroll
        for (int k = 0; k < I_ / 2; ++k) w2[k] = wrow[k];
    }
    float bias = b_ih[g];
    __syncthreads();

    for (int r = 0; r < 64; ++r) {
        unsigned long long acc0 = pack2_(bias, 0.f);
        unsigned long long acc1 = pack2_(0.f, 0.f);
        const ulonglong2* row8 = (const ulonglong2*)(xs + r * I_);
#pragma unroll
        for (int k = 0; k < I_ / 4; ++k) {
            ulonglong2 v = row8[k];
            fma2_(acc0, w2[2 * k + 0], v.x);
            fma2_(acc1, w2[2 * k + 1], v.y);
        }
        float2 a0 = unpack2_(acc0);
        float2 a1 = unpack2_(acc1);
        g_xp[(long)(m0 + r) * G_ + g] = (a0.x + a1.x) + (a0.y + a1.y);
    }
}

// ---------------------------------------------------------------------------
// Kernel 3: GRU scan. One CTA per batch, 768 threads (K-split by 2).
// Thread (half, g): 64-wide half of W_hh row g -> 32 f32x2 regs (64 regs).
// Partials meet in smem; gates on threads 0..127; 2 barriers/step.
// gi streamed with prefetch depth 2.
// ---------------------------------------------------------------------------
__global__ __launch_bounds__(768, 1) void gru_kernel(
    const float* __restrict__ W_hh, const float* __restrict__ b_hh,
    const float* __restrict__ W_fc, const float* __restrict__ b_fc,
    float* __restrict__ out) {
    __shared__ __align__(16) float sh[H_];   // hidden state
    __shared__ float sP[2][G_];              // matvec partials per K-half
    __shared__ float sGn[H_];                // i_n (kept unsummed)

    int tid = threadIdx.x;
    int half = (tid >= G_) ? 1 : 0;
    int g = tid - half * G_;
    int b = blockIdx.x;

    // 64-wide half-row of W_hh in registers (32 x f32x2)
    unsigned long long w2[H_ / 4];
    {
        const unsigned long long* wrow =
            (const unsigned long long*)(W_hh + g * H_ + half * (H_ / 2));
#pragma unroll
        for (int k = 0; k < H_ / 4; ++k) w2[k] = wrow[k];
    }
    unsigned long long biasp =
        pack2_(half ? 0.f : b_hh[g], 0.f);   // fold bias into half-0 acc

    if (tid < H_) sh[tid] = 0.f;

    // gi stream, prefetch depth 2 (half-0 threads only)
    const float* gp = g_xp + (long)b * T_ * G_ + g;
    float gi0 = 0.f, gi1 = 0.f;
    if (!half) {
        gi0 = gp[0];
        gi1 = gp[G_];
        gp += 2 * G_;                         // now points at row t=2
    }
    __syncthreads();

    const ulonglong2* h8 = (const ulonglong2*)(sh + half * (H_ / 2));

    for (int t = 0; t < T_; ++t) {
        float gi2 = 0.f;
        if (!half) { gi2 = *gp; gp += G_; }   // prefetch t+2 (padded tail)

        unsigned long long acc = biasp;
#pragma unroll
        for (int k = 0; k < H_ / 8; ++k) {
            ulonglong2 hv = h8[k];            // LDS.128, warp-broadcast
            fma2_(acc, w2[2 * k + 0], hv.x);
            fma2_(acc, w2[2 * k + 1], hv.y);
        }
        float2 a = unpack2_(acc);
        float s = a.x + a.y;

        if (!half) {
            if (g < 2 * H_) s += gi0;         // r,z: fold gi into pre-act
            else            sGn[g - 2 * H_] = gi0;  // n: keep i_n separate
        }
        sP[half][g] = s;
        __syncthreads();

        if (tid < H_) {
            float Ar  = sP[0][tid]          + sP[1][tid];
            float Az  = sP[0][tid + H_]     + sP[1][tid + H_];
            float ghn = sP[0][tid + 2 * H_] + sP[1][tid + 2 * H_];
            float r = sigm_(Ar);
            float z = sigm_(Az);
            float n = tanh_(fmaf(r, ghn, sGn[tid]));
            sh[tid] = (1.f - z) * n + z * sh[tid];
        }
        __syncthreads();
        gi0 = gi1;
        gi1 = gi2;
    }

    if (tid < C_) {
        float o = b_fc[tid];
        const float* wf = W_fc + tid * H_;
#pragma unroll 8
        for (int j = 0; j < H_; ++j) o = fmaf(sh[j], wf[j], o);
        o = (o - BETA_ * g_st12[b * C_ + tid]) / (1.f - BETA_);
        o = (o - ALPHA_ * g_st11[b * C_ + tid]) / (1.f - ALPHA_);
        out[b * C_ + tid] = o;
    }
}

// ---------------------------------------------------------------------------
extern "C" void kernel_launch(void* const* d_in, const int* in_sizes, int n_in,
                              void* d_out, int out_size) {
    const float* x    = (const float*)d_in[0];
    const float* W_ih = (const float*)d_in[1];
    const float* W_hh = (const float*)d_in[2];
    const float* b_ih = (const float*)d_in[3];
    const float* b_hh = (const float*)d_in[4];
    const float* W_fc = (const float*)d_in[5];
    const float* b_fc = (const float*)d_in[6];
    float* out = (float*)d_out;

    ema_kernel<<<B_ * (T_ / CH_), 64>>>(x);
    xp_gemm_kernel<<<(B_ * T_) / 64, 384>>>(W_ih, b_ih);
    gru_kernel<<<B_, 768>>>(W_hh, b_hh, W_fc, b_fc, out);
}